// round 17
// baseline (speedup 1.0000x reference)
#include <cuda_runtime.h>
#include <cstdint>
#include <cstddef>

// ---------------- problem constants ----------------
#define ND    10000
#define NG    100000
#define EDD   160000
#define EGG   1600000
#define EDT   500000
#define ETD   500000

#define BD_BLK ((ND + 63) / 64)
#define BG_BLK ((NG + 63) / 64)
#define GEMM_GRID (2 * (BD_BLK + BG_BLK))
#define TOTH ((long long)EDD + EGG + ETD + EDT + ETD + EDT)
#define HIST_BLOCKS ((int)((TOTH + 255) / 256))

// ---------------- scratch: __device__ globals ----------------
__device__ float g_h0[(size_t)ND * 64];         // dd branch GEMM out (drug sources)
__device__ float g_h1[(size_t)NG * 64];         // td branch GEMM out (gene sources)
__device__ float g_h2[(size_t)NG * 64];         // gg branch GEMM out (gene sources)
__device__ float g_h3[(size_t)ND * 64];         // dt branch GEMM out (drug sources)
__device__ float g_agg_da[(size_t)ND * 64];     // normalized branch results
__device__ float g_agg_db[(size_t)ND * 64];
__device__ float g_agg_ga[(size_t)NG * 64];
__device__ float g_agg_gb[(size_t)NG * 64];

// CSR (by target node) per edge type: 0=dd, 1=gg, 2=td, 3=dt
__device__ int g_off_dd[ND + 1], g_off_td[ND + 1];
__device__ int g_off_gg[NG + 1], g_off_dt[NG + 1];
__device__ int g_curs_dd[ND], g_curs_td[ND];
__device__ int g_curs_gg[NG], g_curs_dt[NG];
__device__ int g_src_dd[EDD], g_src_gg[EGG], g_src_td[ETD], g_src_dt[EDT];

// histograms -- INVARIANT: zero at kernel_launch entry (BSS init on first run;
// scan6 re-zeros each array immediately after consuming it on every run).
__device__ int g_ht_dd[ND], g_ht_td[ND], g_hs_dt[ND];
__device__ int g_ht_gg[NG], g_ht_dt[NG], g_hs_td[NG];

// dinv
__device__ float g_dinv_dd[ND], g_dinv_t_td[ND], g_dinv_s_dt[ND];
__device__ float g_dinv_gg[NG], g_dinv_s_td[NG], g_dinv_t_dt[NG];

// ---------------- device-side selectors ----------------
__device__ __forceinline__ int* hist_ptr(int s) {
    switch (s) {
        case 0: return g_ht_dd; case 1: return g_ht_gg; case 2: return g_ht_td;
        case 3: return g_ht_dt; case 4: return g_hs_td; default: return g_hs_dt;
    }
}
__device__ __forceinline__ int* off_ptr(int et) {
    switch (et) { case 0: return g_off_dd; case 1: return g_off_gg;
                  case 2: return g_off_td; default: return g_off_dt; }
}
__device__ __forceinline__ int* curs_ptr(int et) {
    switch (et) { case 0: return g_curs_dd; case 1: return g_curs_gg;
                  case 2: return g_curs_td; default: return g_curs_dt; }
}
__device__ __forceinline__ int* src_ptr(int et) {
    switch (et) { case 0: return g_src_dd; case 1: return g_src_gg;
                  case 2: return g_src_td; default: return g_src_dt; }
}
__device__ __forceinline__ int tgt_n(int et) {
    switch (et) { case 0: case 2: return ND; default: return NG; }
}

// ---------------- threefry2x32 (JAX-compatible) ----------------
__host__ __device__ __forceinline__ uint32_t rotl32(uint32_t v, int r) {
    return (v << r) | (v >> (32 - r));
}
__host__ __device__ __forceinline__ void tf2x32(uint32_t k0, uint32_t k1,
                                                uint32_t x0, uint32_t x1,
                                                uint32_t& o0, uint32_t& o1) {
    uint32_t ks0 = k0, ks1 = k1, ks2 = k0 ^ k1 ^ 0x1BD11BDAu;
    x0 += ks0; x1 += ks1;
#define TFR(r) { x0 += x1; x1 = rotl32(x1, r); x1 ^= x0; }
    TFR(13) TFR(15) TFR(26) TFR(6)
    x0 += ks1; x1 += ks2 + 1u;
    TFR(17) TFR(29) TFR(16) TFR(24)
    x0 += ks2; x1 += ks0 + 2u;
    TFR(13) TFR(15) TFR(26) TFR(6)
    x0 += ks0; x1 += ks1 + 3u;
    TFR(17) TFR(29) TFR(16) TFR(24)
    x0 += ks1; x1 += ks2 + 4u;
    TFR(13) TFR(15) TFR(26) TFR(6)
    x0 += ks2; x1 += ks0 + 5u;
#undef TFR
    o0 = x0; o1 = x1;
}

// keep iff uniform(bits) < 0.8f, exactly, in integer domain
__device__ __forceinline__ bool keep_bit(uint32_t bits) {
    return (bits >> 9) < 6710887u;
}

// ---------------- fused dropout + 4-branch GEMM (+ optional hist tail) ----------------
struct GemmArgs {
    const float* W[4];
    uint32_t k0[4], k1[4];
};

struct EdgePtrs {
    const int *t_dd, *t_gg, *t_td, *t_dt, *s_td, *s_dt;
};

__device__ __forceinline__ void hist_body(long long i, const EdgePtrs& ep) {
    const long long B0 = EDD, B1 = B0 + EGG, B2 = B1 + ETD, B3 = B2 + EDT,
                    B4 = B3 + ETD, B5 = B4 + EDT;
    int v, nmax; int* hist;
    if (i < B0)      { v = ep.t_dd[i];      hist = g_ht_dd; nmax = ND; }
    else if (i < B1) { v = ep.t_gg[i - B0]; hist = g_ht_gg; nmax = NG; }
    else if (i < B2) { v = ep.t_td[i - B1]; hist = g_ht_td; nmax = ND; }
    else if (i < B3) { v = ep.t_dt[i - B2]; hist = g_ht_dt; nmax = NG; }
    else if (i < B4) { v = ep.s_td[i - B3]; hist = g_hs_td; nmax = NG; }
    else if (i < B5) { v = ep.s_dt[i - B4]; hist = g_hs_dt; nmax = ND; }
    else return;
    if ((unsigned)v < (unsigned)nmax) atomicAdd(&hist[v], 1);
}

// Blocks [0, GEMM_GRID): the 4-branch GEMM. Blocks [GEMM_GRID, +HIST_BLOCKS):
// edge histograms (layer 0 only) -- independent work co-scheduled to overlap
// mem-latency-bound atomics with the alu-bound GEMM.
template<int K, int WITH_HIST>
__global__ __launch_bounds__(256)
void gemm4_kernel(const float* __restrict__ drug_x, const float* __restrict__ gene_x,
                  int layer, GemmArgs a, EdgePtrs ep) {
    __shared__ float Ws[64 * 64];
    __shared__ float Xs[64 * 65];
    int bid = blockIdx.x;
    if (WITH_HIST && bid >= GEMM_GRID) {
        long long i = (long long)(bid - GEMM_GRID) * 256 + threadIdx.x;
        hist_body(i, ep);
        return;
    }
    const int BD = BD_BLK, BG = BG_BLK;
    int br, rb, n;
    if (bid < BD)               { br = 0; rb = bid;                 n = ND; }
    else if (bid < BD + BG)     { br = 1; rb = bid - BD;            n = NG; }
    else if (bid < BD + 2 * BG) { br = 2; rb = bid - BD - BG;       n = NG; }
    else                        { br = 3; rb = bid - BD - 2 * BG;   n = ND; }
    int row0 = rb << 6;
    bool drug_in = (br == 0 || br == 3);
    const float* X  = drug_in ? drug_x : gene_x;
    const float* XA = drug_in ? g_agg_da : g_agg_ga;
    const float* XB = drug_in ? g_agg_db : g_agg_gb;
    float* Hm = (br == 0) ? g_h0 : (br == 1) ? g_h1 : (br == 2) ? g_h2 : g_h3;
    const float* W = a.W[br];
    uint32_t k0 = a.k0[br], k1 = a.k1[br];

    int tid = threadIdx.x;
    int tx = tid & 15, ty = tid >> 4;
    float acc[4][4];
#pragma unroll
    for (int j = 0; j < 4; j++)
#pragma unroll
        for (int q = 0; q < 4; q++) acc[j][q] = 0.0f;

    for (int kc = 0; kc < K; kc += 64) {
        for (int i = tid; i < 64 * 64; i += 256) {
            int k = i >> 6, cc = i & 63;
            Ws[i] = W[(size_t)(kc + k) * 64 + cc];
        }
        // X tile load with fused JAX-threefry dropout (bits = o0 ^ o1)
        for (int i = tid; i < 64 * 64; i += 256) {
            int r = i >> 6, k = i & 63;
            int gr = row0 + r;
            float v = 0.0f;
            if (gr < n) {
                uint32_t idx = (uint32_t)gr * (uint32_t)K + (uint32_t)(kc + k);
                uint32_t o0, o1;
                tf2x32(k0, k1, 0u, idx, o0, o1);
                float xv = layer ? (XA[idx] + XB[idx]) : X[idx];
                v = keep_bit(o0 ^ o1) ? xv * 1.25f : 0.0f;
            }
            Xs[r * 65 + k] = v;
        }
        __syncthreads();
#pragma unroll 8
        for (int k = 0; k < 64; k++) {
            float4 w = *(const float4*)&Ws[(k << 6) + (tx << 2)];
#pragma unroll
            for (int j = 0; j < 4; j++) {
                float xv = Xs[(ty + (j << 4)) * 65 + k];
                acc[j][0] = fmaf(xv, w.x, acc[j][0]);
                acc[j][1] = fmaf(xv, w.y, acc[j][1]);
                acc[j][2] = fmaf(xv, w.z, acc[j][2]);
                acc[j][3] = fmaf(xv, w.w, acc[j][3]);
            }
        }
        __syncthreads();
    }
#pragma unroll
    for (int j = 0; j < 4; j++) {
        int r = row0 + ty + (j << 4);
        if (r < n) {
            float4 o = make_float4(acc[j][0], acc[j][1], acc[j][2], acc[j][3]);
            *(float4*)&Hm[(size_t)r * 64 + (tx << 2)] = o;
        }
    }
}

// ---------------- scan6: scan + dinv + hist-re-zero, 6 concurrent blocks ----------------
__device__ __forceinline__ float dinv_of(int c) {
    return (c > 0) ? (1.0f / sqrtf((float)c)) : 0.0f;
}

// blocks 0-3: exclusive scan of target hist (CSR offsets + cursors) AND target
//             dinv AND re-zero the hist (each thread zeroes only its own chunk,
//             which only it reads -- no sync needed).
// blocks 4-5: source dinv + re-zero source hist.
__global__ void scan6_kernel() {
    __shared__ int tsum[1024];
    int b = blockIdx.x;
    int tid = threadIdx.x;
    if (b < 4) {
        int et = b;
        int n = tgt_n(et);
        int* cnt = hist_ptr(et);
        int* off = off_ptr(et);
        int* cur = curs_ptr(et);
        float* dv = (et == 0) ? g_dinv_dd : (et == 1) ? g_dinv_gg
                  : (et == 2) ? g_dinv_t_td : g_dinv_t_dt;
        int self = (et <= 1) ? 1 : 0;
        int chunk = (n + 1023) >> 10;
        int lo = tid * chunk;
        int hi = min(lo + chunk, n);
        int s = 0;
        for (int i = lo; i < hi; i++) s += cnt[i];
        tsum[tid] = s;
        __syncthreads();
        for (int o = 1; o < 1024; o <<= 1) {
            int v = (tid >= o) ? tsum[tid - o] : 0;
            __syncthreads();
            tsum[tid] += v;
            __syncthreads();
        }
        int run = (tid > 0) ? tsum[tid - 1] : 0;
        for (int i = lo; i < hi; i++) {
            int c = cnt[i];
            off[i] = run; cur[i] = run; run += c;
            dv[i] = dinv_of(c + self);
            cnt[i] = 0;                       // restore invariant for next replay
        }
        if (tid == 1023) off[n] = tsum[1023];
    } else if (b == 4) {                      // td source degrees (genes)
        for (int i = tid; i < NG; i += 1024) {
            g_dinv_s_td[i] = dinv_of(g_hs_td[i]);
            g_hs_td[i] = 0;
        }
    } else {                                  // dt source degrees (drugs)
        for (int i = tid; i < ND; i += 1024) {
            g_dinv_s_dt[i] = dinv_of(g_hs_dt[i]);
            g_hs_dt[i] = 0;
        }
    }
}

__global__ void scatter_all_kernel(const int* __restrict__ ei_dd, const int* __restrict__ ei_gg,
                                   const int* __restrict__ ei_td, const int* __restrict__ ei_dt) {
    int i = blockIdx.x * blockDim.x + threadIdx.x;
    const int B0 = EDD, B1 = B0 + EGG, B2 = B1 + ETD, B3 = B2 + EDT;
    int et, e, E; const int* ei;
    if (i < B0)      { et = 0; e = i;      ei = ei_dd; E = EDD; }
    else if (i < B1) { et = 1; e = i - B0; ei = ei_gg; E = EGG; }
    else if (i < B2) { et = 2; e = i - B1; ei = ei_td; E = ETD; }
    else if (i < B3) { et = 3; e = i - B2; ei = ei_dt; E = EDT; }
    else return;
    int c = ei[E + e];                          // target
    if ((unsigned)c >= (unsigned)tgt_n(et)) return;
    int p = atomicAdd(&curs_ptr(et)[c], 1);
    if (p >= 0 && p < E) src_ptr(et)[p] = ei[e];  // source
}

// ---------------- 4-branch CSR gather + bias/relu/L2norm ----------------
__global__ void gather4_kernel(const float* __restrict__ bdd, const float* __restrict__ btd,
                               const float* __restrict__ bgg, const float* __restrict__ bdt) {
    int idx = blockIdx.x * blockDim.x + threadIdx.x;
    const int S0 = ND * 16, S1 = 2 * ND * 16, S2 = (2 * ND + NG) * 16,
              TOT = (2 * ND + 2 * NG) * 16;
    if (idx >= TOT) return;
    int local, et, self;
    const float *Hm, *dinvs, *dinvt, *bias;
    float* agg;
    if (idx < S0)      { local = idx;      et = 0; dinvs = g_dinv_dd;   dinvt = g_dinv_dd;
                         self = 1; Hm = g_h0; agg = g_agg_da; bias = bdd; }
    else if (idx < S1) { local = idx - S0; et = 2; dinvs = g_dinv_s_td; dinvt = g_dinv_t_td;
                         self = 0; Hm = g_h1; agg = g_agg_db; bias = btd; }
    else if (idx < S2) { local = idx - S1; et = 1; dinvs = g_dinv_gg;   dinvt = g_dinv_gg;
                         self = 1; Hm = g_h2; agg = g_agg_ga; bias = bgg; }
    else               { local = idx - S2; et = 3; dinvs = g_dinv_s_dt; dinvt = g_dinv_t_dt;
                         self = 0; Hm = g_h3; agg = g_agg_gb; bias = bdt; }
    int node = local >> 4, c = local & 15;
    const int* off = off_ptr(et);
    const int* srcarr = src_ptr(et);

    int b = off[node], e = off[node + 1];
    float ax = 0.f, ay = 0.f, az = 0.f, aw = 0.f;
    for (int p = b; p < e; p++) {
        int s = __ldg(srcarr + p);
        float ns = __ldg(dinvs + s);
        float4 v = __ldg((const float4*)(Hm + (size_t)s * 64 + (c << 2)));
        ax = fmaf(ns, v.x, ax);
        ay = fmaf(ns, v.y, ay);
        az = fmaf(ns, v.z, az);
        aw = fmaf(ns, v.w, aw);
    }
    float dtv = dinvt[node];
    ax *= dtv; ay *= dtv; az *= dtv; aw *= dtv;
    if (self) {
        float4 v = *(const float4*)(Hm + (size_t)node * 64 + (c << 2));
        float w = dtv * dtv;
        ax = fmaf(w, v.x, ax);
        ay = fmaf(w, v.y, ay);
        az = fmaf(w, v.z, az);
        aw = fmaf(w, v.w, aw);
    }
    // bias + relu
    float4 bb = __ldg((const float4*)(bias + (c << 2)));
    ax = fmaxf(ax + bb.x, 0.0f);
    ay = fmaxf(ay + bb.y, 0.0f);
    az = fmaxf(az + bb.z, 0.0f);
    aw = fmaxf(aw + bb.w, 0.0f);
    // L2 norm across this node's 16 chunk-threads (aligned 16-lane group)
    float ss = ax * ax + ay * ay + az * az + aw * aw;
#pragma unroll
    for (int o = 8; o > 0; o >>= 1) ss += __shfl_xor_sync(0xffffffffu, ss, o, 16);
    float den = fmaxf(sqrtf(ss), 1e-12f);
    float4 o4 = make_float4(ax / den, ay / den, az / den, aw / den);
    *(float4*)(agg + (size_t)node * 64 + (c << 2)) = o4;
}

// ---------------- final add (layer 1 only): out = aggA + aggB ----------------
__global__ void add2_kernel(float* __restrict__ out) {
    int i = blockIdx.x * blockDim.x + threadIdx.x;
    const int NDQ = ND * 16, NGQ = NG * 16;     // float4 counts
    if (i < NDQ) {
        float4 a = ((const float4*)g_agg_da)[i];
        float4 b = ((const float4*)g_agg_db)[i];
        ((float4*)out)[i] = make_float4(a.x + b.x, a.y + b.y, a.z + b.z, a.w + b.w);
    } else if (i < NDQ + NGQ) {
        int j = i - NDQ;
        float4 a = ((const float4*)g_agg_ga)[j];
        float4 b = ((const float4*)g_agg_gb)[j];
        ((float4*)out)[i] = make_float4(a.x + b.x, a.y + b.y, a.z + b.z, a.w + b.w);
    }
}

// ---------------- host orchestration ----------------
namespace {
struct Key2 { uint32_t k0, k1; };
inline int cdiv(long long a, int b) { return (int)((a + b - 1) / b); }
}

extern "C" void kernel_launch(void* const* d_in, const int* in_sizes, int n_in,
                              void* d_out, int out_size) {
    // ---- resolve inputs by SIZE (confirmed working) ----
    int idx_drug = -1, idx_gene = -1, idx_eidd = -1, idx_eigg = -1;
    int idx_1m[2] = {-1, -1}; int n1m = 0;
    int idx_w0[4] = {-1, -1, -1, -1}; int nw0 = 0;
    int idx_w1[4] = {-1, -1, -1, -1}; int nw1 = 0;
    int idx_b[8]  = {-1, -1, -1, -1, -1, -1, -1, -1}; int nb = 0;
    for (int i = 0; i < n_in; i++) {
        int s = in_sizes[i];
        if      (s == ND * 128)  idx_drug = i;
        else if (s == NG * 128)  idx_gene = i;
        else if (s == 2 * EDD)   idx_eidd = i;
        else if (s == 2 * EGG)   idx_eigg = i;
        else if (s == 2 * EDT)   { if (n1m < 2) idx_1m[n1m++] = i; }
        else if (s == 128 * 64)  { if (nw0 < 4) idx_w0[nw0++] = i; }
        else if (s == 64 * 64)   { if (nw1 < 4) idx_w1[nw1++] = i; }
        else if (s == 64)        { if (nb < 8)  idx_b[nb++]  = i; }
    }
    bool dict_order = (idx_eidd >= 0 && nw0 > 0 && idx_eidd < idx_w0[0]);

    const float* drug_x = (const float*)d_in[idx_drug];
    const float* gene_x = (const float*)d_in[idx_gene];
    const int* ei_dd = (const int*)d_in[idx_eidd];
    const int* ei_gg = (const int*)d_in[idx_eigg];
    const int* ei_dt = (const int*)d_in[dict_order ? idx_1m[0] : idx_1m[1]];
    const int* ei_td = (const int*)d_in[dict_order ? idx_1m[1] : idx_1m[0]];
    const float* Wl[2][4];
    const float* bl[2][4];
    for (int e = 0; e < 4; e++) {
        Wl[0][e] = (const float*)d_in[idx_w0[e]];
        Wl[1][e] = (const float*)d_in[idx_w1[e]];
        for (int l = 0; l < 2; l++)
            bl[l][e] = (const float*)d_in[idx_b[dict_order ? (e * 2 + l) : (l * 4 + e)]];
    }
    float* out = (float*)d_out;

    // ---- JAX dropout keys (threefry, partitionable), host-side ----
    Key2 kk[2][4];
    for (int l = 0; l < 2; l++) {
        uint32_t f0, f1;
        tf2x32(0u, 42u, 0u, (uint32_t)l, f0, f1);
        for (int j = 0; j < 4; j++)
            tf2x32(f0, f1, 0u, (uint32_t)j, kk[l][j].k0, kk[l][j].k1);
    }

    GemmArgs ga[2];
    for (int l = 0; l < 2; l++) {
        ga[l].k0[0] = kk[l][0].k0; ga[l].k1[0] = kk[l][0].k1;   // dd: drug dropout
        ga[l].k0[1] = kk[l][1].k0; ga[l].k1[1] = kk[l][1].k1;   // td: gene dropout
        ga[l].k0[2] = kk[l][2].k0; ga[l].k1[2] = kk[l][2].k1;   // gg: gene dropout
        ga[l].k0[3] = kk[l][3].k0; ga[l].k1[3] = kk[l][3].k1;   // dt: drug dropout
        // W order in gemm4 branches: 0=Wdd, 1=Wtd, 2=Wgg, 3=Wdt
        ga[l].W[0] = Wl[l][0]; ga[l].W[1] = Wl[l][2]; ga[l].W[2] = Wl[l][1]; ga[l].W[3] = Wl[l][3];
    }

    EdgePtrs ep;
    ep.t_dd = ei_dd + EDD; ep.t_gg = ei_gg + EGG; ep.t_td = ei_td + ETD;
    ep.t_dt = ei_dt + EDT; ep.s_td = ei_td;       ep.s_dt = ei_dt;

    const long long TOTS = (long long)EDD + EGG + ETD + EDT;
    const long long TOTG = (long long)(2 * ND + 2 * NG) * 16;
    const long long TOTA = (long long)(ND + NG) * 16;

    // ---- 7-node graph ----
    // 1) gemm4-L0 with hist blocks fused in (independent; overlaps alu-bound
    //    GEMM with mem-latency-bound edge atomics; hists are zero by invariant)
    gemm4_kernel<128, 1><<<GEMM_GRID + HIST_BLOCKS, 256>>>(drug_x, gene_x, 0, ga[0], ep);
    // 2) scan + dinv + hist re-zero
    scan6_kernel<<<6, 1024>>>();
    // 3) CSR source scatter
    scatter_all_kernel<<<cdiv(TOTS, 256), 256>>>(ei_dd, ei_gg, ei_td, ei_dt);
    // 4) layer-0 gather (+bias/relu/L2norm)
    gather4_kernel<<<cdiv(TOTG, 256), 256>>>(bl[0][0], bl[0][2], bl[0][1], bl[0][3]);
    // 5) layer-1 GEMM (reads aggA+aggB directly)
    gemm4_kernel<64, 0><<<GEMM_GRID, 256>>>(drug_x, gene_x, 1, ga[1], ep);
    // 6) layer-1 gather
    gather4_kernel<<<cdiv(TOTG, 256), 256>>>(bl[1][0], bl[1][2], bl[1][1], bl[1][3]);
    // 7) final combine
    add2_kernel<<<cdiv(TOTA, 256), 256>>>(out);
}